// round 2
// baseline (speedup 1.0000x reference)
#include <cuda_runtime.h>
#include <math.h>

#define BATCH 2
#define SEQ   2048
#define NH    16
#define HD    64
#define EMB   1024
#define MTOT  (BATCH*SEQ)
#define PADW  68

// Scratch (allocation-free): Q/K/V in [b][h][s][d] layout, 16 MB each.
static __device__ float g_q[BATCH*NH*SEQ*HD];
static __device__ float g_k[BATCH*NH*SEQ*HD];
static __device__ float g_v[BATCH*NH*SEQ*HD];

// ---------------------------------------------------------------------------
// QKV projection: C[m][n] = sum_k X[m][k] * W[n][k] + bias[n]
// 64x64 block tile, BK=16, 4x4 per thread. grid.z selects Q/K/V.
// Epilogue scatters into [b][h][s][d] scratch.
// ---------------------------------------------------------------------------
__global__ __launch_bounds__(256) void qkv_gemm_kernel(
    const float* __restrict__ X,
    const float* __restrict__ Wq, const float* __restrict__ bq,
    const float* __restrict__ Wk, const float* __restrict__ bk,
    const float* __restrict__ Wv, const float* __restrict__ bv)
{
    const float *W, *bias;
    float *out;
    if (blockIdx.z == 0)      { W = Wq; bias = bq; out = g_q; }
    else if (blockIdx.z == 1) { W = Wk; bias = bk; out = g_k; }
    else                      { W = Wv; bias = bv; out = g_v; }

    __shared__ float Xs[16][64];
    __shared__ float Ws[16][64];

    const int tid = threadIdx.x;
    const int tx = tid & 15, ty = tid >> 4;
    const int m0 = blockIdx.y * 64;
    const int n0 = blockIdx.x * 64;
    const int lrow = tid >> 2;        // 0..63
    const int lk4  = (tid & 3) << 2;  // 0,4,8,12

    const float* xg = X + (size_t)(m0 + lrow) * EMB + lk4;
    const float* wg = W + (size_t)(n0 + lrow) * EMB + lk4;

    float acc[4][4] = {};
    for (int k0 = 0; k0 < EMB; k0 += 16) {
        float4 xv = *(const float4*)(xg + k0);
        float4 wv = *(const float4*)(wg + k0);
        __syncthreads();
        Xs[lk4+0][lrow] = xv.x; Xs[lk4+1][lrow] = xv.y;
        Xs[lk4+2][lrow] = xv.z; Xs[lk4+3][lrow] = xv.w;
        Ws[lk4+0][lrow] = wv.x; Ws[lk4+1][lrow] = wv.y;
        Ws[lk4+2][lrow] = wv.z; Ws[lk4+3][lrow] = wv.w;
        __syncthreads();
        #pragma unroll
        for (int kk = 0; kk < 16; kk++) {
            float4 xr = *(const float4*)&Xs[kk][ty << 2];
            float4 wr = *(const float4*)&Ws[kk][tx << 2];
            float xa[4] = {xr.x, xr.y, xr.z, xr.w};
            float wa[4] = {wr.x, wr.y, wr.z, wr.w};
            #pragma unroll
            for (int i = 0; i < 4; i++)
                #pragma unroll
                for (int j = 0; j < 4; j++)
                    acc[i][j] += xa[i] * wa[j];
        }
    }

    const int b = m0 / SEQ;
    const int h = n0 / HD;
    const int dd0 = (n0 - h*HD) + (tx << 2);   // 0..60, multiple of 4
    float4 bvv = *(const float4*)&bias[n0 + (tx << 2)];
    float ba[4] = {bvv.x, bvv.y, bvv.z, bvv.w};
    #pragma unroll
    for (int i = 0; i < 4; i++) {
        int m = m0 + (ty << 2) + i;
        int s = m - b*SEQ;
        float4 o;
        o.x = acc[i][0] + ba[0];
        o.y = acc[i][1] + ba[1];
        o.z = acc[i][2] + ba[2];
        o.w = acc[i][3] + ba[3];
        *(float4*)&out[(((size_t)(b*NH + h))*SEQ + s)*HD + dd0] = o;
    }
}

// ---------------------------------------------------------------------------
// RoPE in place on g_q and g_k. One thread per (tensor, b, h, s, i<32) pair.
// q'[i]    = q[i]*cos(f_i)    - q[i+32]*sin(f_i)
// q'[i+32] = q[i+32]*cos(f_i) + q[i]*sin(f_i),  f_i = s * 10000^(-i/32)
// ---------------------------------------------------------------------------
__global__ void rope_kernel()
{
    int idx = blockIdx.x * blockDim.x + threadIdx.x;
    const int per = BATCH*NH*SEQ*32;      // 2^21
    if (idx >= 2*per) return;
    float* buf = g_q;
    if (idx >= per) { buf = g_k; idx -= per; }
    const int i  = idx & 31;
    const int s  = (idx >> 5) & (SEQ - 1);
    const int bh = idx >> 16;             // 0..31
    const float inv = expf(-(float)i * (logf(10000.0f) / 32.0f));
    const float f = (float)s * inv;
    float sn, cs;
    sincosf(f, &sn, &cs);
    const size_t base = ((size_t)bh * SEQ + s) * HD;
    const float lo = buf[base + i];
    const float hi = buf[base + i + 32];
    buf[base + i]      = lo*cs - hi*sn;
    buf[base + i + 32] = hi*cs + lo*sn;
}

// ---------------------------------------------------------------------------
// Flash attention: one block per (b, h, 64-row q tile). Br=Bc=64, d=64.
// 16x16 thread grid, 4x4 per thread. Online softmax, shfl row reductions.
// Smem: QT[kk][r], KT[kk][c], VS[kk][c], PT[c][r]  each [64][PADW].
// ---------------------------------------------------------------------------
__global__ __launch_bounds__(256) void flash_kernel(
    const float* __restrict__ mask, float* __restrict__ out)
{
    extern __shared__ float sm[];
    float* QT = sm;                 // QT[kk*PADW + r] = Q[r][kk]
    float* KT = sm + 64*PADW;       // KT[kk*PADW + c] = K[c][kk]
    float* VS = sm + 2*64*PADW;     // VS[kk*PADW + c] = V[kk][c]
    float* PT = sm + 3*64*PADW;     // PT[c*PADW + r]  = P[r][c]

    const int tid = threadIdx.x;
    const int tx = tid & 15, ty = tid >> 4;
    const int q0 = blockIdx.x * 64;
    const int h  = blockIdx.y;
    const int b  = blockIdx.z;

    const size_t hbase = ((size_t)(b*NH + h)) * SEQ * HD;
    const float* qg = g_q + hbase;
    const float* kg = g_k + hbase;
    const float* vg = g_v + hbase;
    const float* mk = mask + (size_t)b * SEQ;

    // Load Q tile transposed (done once)
    #pragma unroll
    for (int i = 0; i < 4; i++) {
        int f = i*256 + tid;
        int row = f >> 4;
        int c4  = (f & 15) << 2;
        float4 v = *(const float4*)(qg + (size_t)(q0 + row)*HD + c4);
        QT[(c4+0)*PADW + row] = v.x;
        QT[(c4+1)*PADW + row] = v.y;
        QT[(c4+2)*PADW + row] = v.z;
        QT[(c4+3)*PADW + row] = v.w;
    }

    float acc[4][4] = {};
    float mprev[4], lsum[4];
    #pragma unroll
    for (int i = 0; i < 4; i++) { mprev[i] = -INFINITY; lsum[i] = 0.f; }

    for (int t = 0; t < SEQ/64; t++) {
        const int k0 = t * 64;

        // Load K (transposed) and V (row-major) tiles
        #pragma unroll
        for (int i = 0; i < 4; i++) {
            int f = i*256 + tid;
            int row = f >> 4;
            int c4  = (f & 15) << 2;
            float4 kv = *(const float4*)(kg + (size_t)(k0 + row)*HD + c4);
            KT[(c4+0)*PADW + row] = kv.x;
            KT[(c4+1)*PADW + row] = kv.y;
            KT[(c4+2)*PADW + row] = kv.z;
            KT[(c4+3)*PADW + row] = kv.w;
            float4 vv = *(const float4*)(vg + (size_t)(k0 + row)*HD + c4);
            *(float4*)&VS[row*PADW + c4] = vv;
        }
        __syncthreads();

        // S = Q K^T  (4x4 per thread)
        float sv[4][4] = {};
        #pragma unroll 4
        for (int kk = 0; kk < 64; kk++) {
            float4 qv = *(const float4*)&QT[kk*PADW + (ty << 2)];
            float4 kv = *(const float4*)&KT[kk*PADW + (tx << 2)];
            float qa[4] = {qv.x, qv.y, qv.z, qv.w};
            float ka[4] = {kv.x, kv.y, kv.z, kv.w};
            #pragma unroll
            for (int i = 0; i < 4; i++)
                #pragma unroll
                for (int j = 0; j < 4; j++)
                    sv[i][j] += qa[i] * ka[j];
        }

        // scale + mask
        float mv[4];
        #pragma unroll
        for (int j = 0; j < 4; j++) mv[j] = mk[k0 + (tx << 2) + j];
        #pragma unroll
        for (int i = 0; i < 4; i++)
            #pragma unroll
            for (int j = 0; j < 4; j++)
                sv[i][j] = sv[i][j] * 0.125f + mv[j];

        // online softmax
        #pragma unroll
        for (int i = 0; i < 4; i++) {
            float rm = fmaxf(fmaxf(sv[i][0], sv[i][1]), fmaxf(sv[i][2], sv[i][3]));
            #pragma unroll
            for (int d = 8; d >= 1; d >>= 1)
                rm = fmaxf(rm, __shfl_xor_sync(0xffffffffu, rm, d));
            float mnew = fmaxf(mprev[i], rm);
            float corr = __expf(mprev[i] - mnew);   // exp(-inf) = 0 on first tile
            float rs = 0.f;
            #pragma unroll
            for (int j = 0; j < 4; j++) {
                float p = __expf(sv[i][j] - mnew);
                PT[((tx << 2) + j)*PADW + (ty << 2) + i] = p;
                rs += p;
            }
            #pragma unroll
            for (int d = 8; d >= 1; d >>= 1)
                rs += __shfl_xor_sync(0xffffffffu, rs, d);
            lsum[i] = lsum[i]*corr + rs;
            #pragma unroll
            for (int j = 0; j < 4; j++) acc[i][j] *= corr;
            mprev[i] = mnew;
        }
        __syncthreads();

        // O += P V
        #pragma unroll 4
        for (int kk = 0; kk < 64; kk++) {
            float4 pv = *(const float4*)&PT[kk*PADW + (ty << 2)];
            float4 vv = *(const float4*)&VS[kk*PADW + (tx << 2)];
            float pa[4] = {pv.x, pv.y, pv.z, pv.w};
            float va[4] = {vv.x, vv.y, vv.z, vv.w};
            #pragma unroll
            for (int i = 0; i < 4; i++)
                #pragma unroll
                for (int j = 0; j < 4; j++)
                    acc[i][j] += pa[i] * va[j];
        }
        __syncthreads();
    }

    // Normalize + write out[b][s][h*64+d]
    #pragma unroll
    for (int i = 0; i < 4; i++) {
        float invl = 1.0f / lsum[i];
        int s = q0 + (ty << 2) + i;
        float4 o;
        o.x = acc[i][0]*invl;
        o.y = acc[i][1]*invl;
        o.z = acc[i][2]*invl;
        o.w = acc[i][3]*invl;
        *(float4*)&out[((size_t)(b*SEQ + s))*EMB + h*HD + (tx << 2)] = o;
    }
}

// ---------------------------------------------------------------------------
extern "C" void kernel_launch(void* const* d_in, const int* in_sizes, int n_in,
                              void* d_out, int out_size)
{
    const float* x    = (const float*)d_in[0];
    const float* mask = (const float*)d_in[1];
    const float* Wq   = (const float*)d_in[2];
    const float* bq   = (const float*)d_in[3];
    const float* Wk   = (const float*)d_in[4];
    const float* bk   = (const float*)d_in[5];
    const float* Wv   = (const float*)d_in[6];
    const float* bv   = (const float*)d_in[7];
    float* out = (float*)d_out;

    dim3 ggrid(EMB/64, MTOT/64, 3);
    qkv_gemm_kernel<<<ggrid, 256>>>(x, Wq, bq, Wk, bk, Wv, bv);

    const int rtot = 2*BATCH*NH*SEQ*32;
    rope_kernel<<<(rtot + 255)/256, 256>>>();

    const int flash_smem = 4*64*PADW*(int)sizeof(float);  // 69632 B
    cudaFuncSetAttribute(flash_kernel,
                         cudaFuncAttributeMaxDynamicSharedMemorySize, flash_smem);
    dim3 fgrid(SEQ/64, NH, BATCH);
    flash_kernel<<<fgrid, 256, flash_smem>>>(mask, out);
}

// round 4
// speedup vs baseline: 2.4836x; 2.4836x over previous
#include <cuda_runtime.h>
#include <math.h>
#include <stdint.h>

#define BATCH 2
#define SEQ   2048
#define NH    16
#define HD    64
#define EMB   1024
#define MTOT  (BATCH*SEQ)

static __device__ float g_q[BATCH*NH*SEQ*HD];
static __device__ float g_k[BATCH*NH*SEQ*HD];
static __device__ float g_v[BATCH*NH*SEQ*HD];

__device__ __forceinline__ uint32_t cvt_tf32(float f) {
    uint32_t r; asm("cvt.rna.tf32.f32 %0, %1;" : "=r"(r) : "f"(f)); return r;
}
__device__ __forceinline__ float f_tf32(float f) { return __uint_as_float(cvt_tf32(f)); }
__device__ __forceinline__ uint32_t fbits(float f) { return __float_as_uint(f); }

__device__ __forceinline__ void mma8(float c[4], const uint32_t a[4], const uint32_t b[2]) {
    asm volatile(
        "mma.sync.aligned.m16n8k8.row.col.f32.tf32.tf32.f32 "
        "{%0,%1,%2,%3}, {%4,%5,%6,%7}, {%8,%9}, {%0,%1,%2,%3};"
        : "+f"(c[0]), "+f"(c[1]), "+f"(c[2]), "+f"(c[3])
        : "r"(a[0]), "r"(a[1]), "r"(a[2]), "r"(a[3]), "r"(b[0]), "r"(b[1]));
}

// ---------------------------------------------------------------------------
// QKV GEMM: C[m][n] = X[m]·W[n] + bias[n].  128x128 CTA tile, 256 threads,
// warp tile 32x64 (4x2 warp grid), K-chunks of 32, double-buffered smem
// [row][36] (pad 4 -> conflict-free fragment lds). tf32 mma, fp32 accum.
// ---------------------------------------------------------------------------
__global__ __launch_bounds__(256) void qkv_gemm_mma(
    const float* __restrict__ X,
    const float* __restrict__ Wq, const float* __restrict__ bq,
    const float* __restrict__ Wk, const float* __restrict__ bk,
    const float* __restrict__ Wv, const float* __restrict__ bv)
{
    const float *W, *bias; float* out;
    if (blockIdx.z == 0)      { W = Wq; bias = bq; out = g_q; }
    else if (blockIdx.z == 1) { W = Wk; bias = bk; out = g_k; }
    else                      { W = Wv; bias = bv; out = g_v; }

    extern __shared__ float sh[];
    float* As[2] = { sh,        sh + 4608 };
    float* Bs[2] = { sh + 9216, sh + 13824 };

    const int tid  = threadIdx.x;
    const int lane = tid & 31;
    const int wid  = tid >> 5;
    const int gid  = lane >> 2;
    const int tig  = lane & 3;
    const int wm   = wid & 3;       // 0..3 -> 32-row band
    const int wn   = wid >> 2;      // 0..1 -> 64-col band
    const int m0 = blockIdx.y * 128;
    const int n0 = blockIdx.x * 128;

    const int lr = tid >> 1;            // 0..127
    const int lc = (tid & 1) * 16;      // 0 | 16
    const float* ag = X + (size_t)(m0 + lr) * EMB + lc;
    const float* bg = W + (size_t)(n0 + lr) * EMB + lc;

    float4 ra[4], rb[4];
    #pragma unroll
    for (int j = 0; j < 4; j++) {
        ra[j] = *(const float4*)(ag + j * 4);
        rb[j] = *(const float4*)(bg + j * 4);
    }

    float acc[2][8][4];
    #pragma unroll
    for (int i = 0; i < 2; i++)
        #pragma unroll
        for (int t = 0; t < 8; t++)
            #pragma unroll
            for (int e = 0; e < 4; e++) acc[i][t][e] = 0.f;

    // store chunk 0
    #pragma unroll
    for (int j = 0; j < 4; j++) {
        float* pa = &As[0][lr * 36 + lc + j * 4];
        float* pb = &Bs[0][lr * 36 + lc + j * 4];
        pa[0]=f_tf32(ra[j].x); pa[1]=f_tf32(ra[j].y); pa[2]=f_tf32(ra[j].z); pa[3]=f_tf32(ra[j].w);
        pb[0]=f_tf32(rb[j].x); pb[1]=f_tf32(rb[j].y); pb[2]=f_tf32(rb[j].z); pb[3]=f_tf32(rb[j].w);
    }
    __syncthreads();

    for (int c = 0; c < 32; c++) {
        const int buf = c & 1;
        if (c < 31) {
            #pragma unroll
            for (int j = 0; j < 4; j++) {
                ra[j] = *(const float4*)(ag + (c + 1) * 32 + j * 4);
                rb[j] = *(const float4*)(bg + (c + 1) * 32 + j * 4);
            }
        }
        const float* A = As[buf];
        const float* B = Bs[buf];
        #pragma unroll
        for (int k8 = 0; k8 < 4; k8++) {
            const int kc = k8 * 8 + tig;
            uint32_t a[2][4];
            #pragma unroll
            for (int i = 0; i < 2; i++) {
                const int r = wm * 32 + i * 16 + gid;
                a[i][0] = fbits(A[r * 36 + kc]);
                a[i][1] = fbits(A[(r + 8) * 36 + kc]);
                a[i][2] = fbits(A[r * 36 + kc + 4]);
                a[i][3] = fbits(A[(r + 8) * 36 + kc + 4]);
            }
            uint32_t b[8][2];
            #pragma unroll
            for (int t = 0; t < 8; t++) {
                const int n = wn * 64 + t * 8 + gid;
                b[t][0] = fbits(B[n * 36 + kc]);
                b[t][1] = fbits(B[n * 36 + kc + 4]);
            }
            #pragma unroll
            for (int i = 0; i < 2; i++)
                #pragma unroll
                for (int t = 0; t < 8; t++)
                    mma8(acc[i][t], a[i], b[t]);
        }
        if (c < 31) {
            __syncthreads();
            const int nb = buf ^ 1;
            #pragma unroll
            for (int j = 0; j < 4; j++) {
                float* pa = &As[nb][lr * 36 + lc + j * 4];
                float* pb = &Bs[nb][lr * 36 + lc + j * 4];
                pa[0]=f_tf32(ra[j].x); pa[1]=f_tf32(ra[j].y); pa[2]=f_tf32(ra[j].z); pa[3]=f_tf32(ra[j].w);
                pb[0]=f_tf32(rb[j].x); pb[1]=f_tf32(rb[j].y); pb[2]=f_tf32(rb[j].z); pb[3]=f_tf32(rb[j].w);
            }
            __syncthreads();
        }
    }

    // epilogue: scatter to [b][h][s][d] with bias
    #pragma unroll
    for (int i = 0; i < 2; i++) {
        const int m = m0 + wm * 32 + i * 16 + gid;
        const int bb = m >> 11;
        const int s  = m & 2047;
        #pragma unroll
        for (int t = 0; t < 8; t++) {
            const int n = n0 + wn * 64 + t * 8 + 2 * tig;
            const int h = n >> 6, dd = n & 63;
            const float b0v = bias[n], b1v = bias[n + 1];
            float* po = &out[(((size_t)(bb * NH + h)) * SEQ + s) * HD + dd];
            *(float2*)po = make_float2(acc[i][t][0] + b0v, acc[i][t][1] + b1v);
            float* po2 = po + 8 * HD;   // row m+8
            *(float2*)po2 = make_float2(acc[i][t][2] + b0v, acc[i][t][3] + b1v);
        }
    }
}

// ---------------------------------------------------------------------------
// RoPE in place on g_q / g_k.
// ---------------------------------------------------------------------------
__global__ void rope_kernel()
{
    int idx = blockIdx.x * blockDim.x + threadIdx.x;
    const int per = BATCH*NH*SEQ*32;
    if (idx >= 2*per) return;
    float* buf = g_q;
    if (idx >= per) { buf = g_k; idx -= per; }
    const int i  = idx & 31;
    const int s  = (idx >> 5) & (SEQ - 1);
    const int bh = idx >> 16;
    const float inv = expf(-(float)i * (logf(10000.0f) / 32.0f));
    float sn, cs;
    sincosf((float)s * inv, &sn, &cs);
    const size_t base = ((size_t)bh * SEQ + s) * HD;
    const float lo = buf[base + i];
    const float hi = buf[base + i + 32];
    buf[base + i]      = lo*cs - hi*sn;
    buf[base + i + 32] = hi*cs + lo*sn;
}

// ---------------------------------------------------------------------------
// Flash attention: CTA = (b, h, 128 q-rows). 128 threads, 4 warps; each warp
// owns 32 full q-rows (warp tile 32 x 64). tf32 mma, fp32 accum, online
// softmax fully inside lane quads. K tiles of 64 keys, 32 iterations.
// smem: Qs[128][68], Ks[64][68], VT[64][68], Ps[128][68], msk[64].
// ---------------------------------------------------------------------------
__global__ __launch_bounds__(128) void flash_mma(const float* __restrict__ mask,
                                                 float* __restrict__ out)
{
    extern __shared__ float sh[];
    float* Qs  = sh;            // 8704 floats
    float* Ks  = sh + 8704;     // 4352
    float* VT  = sh + 13056;    // 4352
    float* Ps  = sh + 17408;    // 8704
    float* msk = sh + 26112;    // 64

    const int tid  = threadIdx.x;
    const int lane = tid & 31;
    const int wid  = tid >> 5;      // 0..3
    const int gid  = lane >> 2;
    const int tig  = lane & 3;
    const int q0 = blockIdx.x * 128;
    const int h  = blockIdx.y;
    const int b  = blockIdx.z;

    const size_t hbase = ((size_t)(b*NH + h)) * SEQ * HD;
    const float* qg = g_q + hbase;
    const float* kg = g_k + hbase;
    const float* vg = g_v + hbase;
    const float* mp = mask + (size_t)b * SEQ;

    // Q tile: one row per thread
    {
        const float* qp = qg + (size_t)(q0 + tid) * HD;
        #pragma unroll
        for (int j = 0; j < 16; j++) {
            float4 v = *(const float4*)(qp + j * 4);
            float* p = &Qs[tid * 68 + j * 4];
            p[0]=f_tf32(v.x); p[1]=f_tf32(v.y); p[2]=f_tf32(v.z); p[3]=f_tf32(v.w);
        }
    }

    float co[2][8][4];
    #pragma unroll
    for (int i = 0; i < 2; i++)
        #pragma unroll
        for (int t = 0; t < 8; t++)
            #pragma unroll
            for (int e = 0; e < 4; e++) co[i][t][e] = 0.f;
    float mR[2][2] = { {-INFINITY, -INFINITY}, {-INFINITY, -INFINITY} };
    float lR[2][2] = { {0.f, 0.f}, {0.f, 0.f} };

    const int krow = tid >> 1;          // 0..63
    const int koff = (tid & 1) * 32;    // 0 | 32

    for (int t = 0; t < 32; t++) {
        __syncthreads();   // protect Ks/VT vs prev-iteration readers
        {
            const float* kp = kg + (size_t)(t * 64 + krow) * HD + koff;
            #pragma unroll
            for (int j = 0; j < 8; j++) {
                float4 v = *(const float4*)(kp + j * 4);
                float* p = &Ks[krow * 68 + koff + j * 4];
                p[0]=f_tf32(v.x); p[1]=f_tf32(v.y); p[2]=f_tf32(v.z); p[3]=f_tf32(v.w);
            }
            const float* vp = vg + (size_t)(t * 64 + krow) * HD + koff;
            #pragma unroll
            for (int j = 0; j < 8; j++) {
                float4 v = *(const float4*)(vp + j * 4);
                VT[(koff + j*4 + 0) * 68 + krow] = f_tf32(v.x);
                VT[(koff + j*4 + 1) * 68 + krow] = f_tf32(v.y);
                VT[(koff + j*4 + 2) * 68 + krow] = f_tf32(v.z);
                VT[(koff + j*4 + 3) * 68 + krow] = f_tf32(v.w);
            }
            if (tid < 64) msk[tid] = mp[t * 64 + tid];
        }
        __syncthreads();

        // ---- S = Q K^T ----
        float cs[2][8][4];
        #pragma unroll
        for (int i = 0; i < 2; i++)
            #pragma unroll
            for (int tt = 0; tt < 8; tt++)
                #pragma unroll
                for (int e = 0; e < 4; e++) cs[i][tt][e] = 0.f;
        #pragma unroll
        for (int k8 = 0; k8 < 8; k8++) {
            const int kc = k8 * 8 + tig;
            uint32_t a[2][4];
            #pragma unroll
            for (int i = 0; i < 2; i++) {
                const int r = wid * 32 + i * 16 + gid;
                a[i][0] = fbits(Qs[r * 68 + kc]);
                a[i][1] = fbits(Qs[(r + 8) * 68 + kc]);
                a[i][2] = fbits(Qs[r * 68 + kc + 4]);
                a[i][3] = fbits(Qs[(r + 8) * 68 + kc + 4]);
            }
            uint32_t bf[8][2];
            #pragma unroll
            for (int tt = 0; tt < 8; tt++) {
                const int n = tt * 8 + gid;
                bf[tt][0] = fbits(Ks[n * 68 + kc]);
                bf[tt][1] = fbits(Ks[n * 68 + kc + 4]);
            }
            #pragma unroll
            for (int i = 0; i < 2; i++)
                #pragma unroll
                for (int tt = 0; tt < 8; tt++)
                    mma8(cs[i][tt], a[i], bf[tt]);
        }

        // ---- online softmax (rows live in lane quads) ----
        #pragma unroll
        for (int i = 0; i < 2; i++) {
            #pragma unroll
            for (int j = 0; j < 2; j++) {
                const int rbase = wid * 32 + i * 16 + j * 8 + gid;
                float rmax = -INFINITY;
                #pragma unroll
                for (int tt = 0; tt < 8; tt++) {
                    float v0 = cs[i][tt][j*2]   * 0.125f + msk[tt*8 + 2*tig];
                    float v1 = cs[i][tt][j*2+1] * 0.125f + msk[tt*8 + 2*tig + 1];
                    cs[i][tt][j*2] = v0; cs[i][tt][j*2+1] = v1;
                    rmax = fmaxf(rmax, fmaxf(v0, v1));
                }
                rmax = fmaxf(rmax, __shfl_xor_sync(0xffffffffu, rmax, 1));
                rmax = fmaxf(rmax, __shfl_xor_sync(0xffffffffu, rmax, 2));
                const float mnew = fmaxf(mR[i][j], rmax);
                const float corr = __expf(mR[i][j] - mnew);
                mR[i][j] = mnew;
                float rsum = 0.f;
                #pragma unroll
                for (int tt = 0; tt < 8; tt++) {
                    float p0 = __expf(cs[i][tt][j*2]   - mnew);
                    float p1 = __expf(cs[i][tt][j*2+1] - mnew);
                    rsum += p0 + p1;
                    *(float2*)&Ps[rbase * 68 + tt * 8 + 2 * tig] =
                        make_float2(f_tf32(p0), f_tf32(p1));
                }
                rsum += __shfl_xor_sync(0xffffffffu, rsum, 1);
                rsum += __shfl_xor_sync(0xffffffffu, rsum, 2);
                lR[i][j] = lR[i][j] * corr + rsum;
                #pragma unroll
                for (int tt = 0; tt < 8; tt++) {
                    co[i][tt][j*2]   *= corr;
                    co[i][tt][j*2+1] *= corr;
                }
            }
        }
        __syncwarp();

        // ---- O += P V ----
        #pragma unroll
        for (int k8 = 0; k8 < 8; k8++) {
            const int kc = k8 * 8 + tig;
            uint32_t a[2][4];
            #pragma unroll
            for (int i = 0; i < 2; i++) {
                const int r = wid * 32 + i * 16 + gid;
                a[i][0] = fbits(Ps[r * 68 + kc]);
                a[i][1] = fbits(Ps[(r + 8) * 68 + kc]);
                a[i][2] = fbits(Ps[r * 68 + kc + 4]);
                a[i][3] = fbits(Ps[(r + 8) * 68 + kc + 4]);
            }
            uint32_t bf[8][2];
            #pragma unroll
            for (int tt = 0; tt < 8; tt++) {
                const int n = tt * 8 + gid;
                bf[tt][0] = fbits(VT[n * 68 + kc]);
                bf[tt][1] = fbits(VT[n * 68 + kc + 4]);
            }
            #pragma unroll
            for (int i = 0; i < 2; i++)
                #pragma unroll
                for (int tt = 0; tt < 8; tt++)
                    mma8(co[i][tt], a[i], bf[tt]);
        }
    }

    // epilogue: normalize rows, write out[b][s][h*64+d]
    #pragma unroll
    for (int i = 0; i < 2; i++) {
        #pragma unroll
        for (int j = 0; j < 2; j++) {
            const float invl = 1.0f / lR[i][j];
            const int row = wid * 32 + i * 16 + j * 8 + gid;
            const int s = q0 + row;
            float* po = &out[((size_t)(b * SEQ + s)) * EMB + h * HD];
            #pragma unroll
            for (int tt = 0; tt < 8; tt++) {
                *(float2*)(po + tt * 8 + 2 * tig) =
                    make_float2(co[i][tt][j*2] * invl, co[i][tt][j*2+1] * invl);
            }
        }
    }
}

// ---------------------------------------------------------------------------
extern "C" void kernel_launch(void* const* d_in, const int* in_sizes, int n_in,
                              void* d_out, int out_size)
{
    const float* x    = (const float*)d_in[0];
    const float* mask = (const float*)d_in[1];
    const float* Wq   = (const float*)d_in[2];
    const float* bq   = (const float*)d_in[3];
    const float* Wk   = (const float*)d_in[4];
    const float* bk   = (const float*)d_in[5];
    const float* Wv   = (const float*)d_in[6];
    const float* bv   = (const float*)d_in[7];
    float* out = (float*)d_out;

    const int gemm_smem  = 18432 * (int)sizeof(float);   // 73728 B
    const int flash_smem = 26176 * (int)sizeof(float);   // 104704 B
    cudaFuncSetAttribute(qkv_gemm_mma, cudaFuncAttributeMaxDynamicSharedMemorySize, gemm_smem);
    cudaFuncSetAttribute(flash_mma,    cudaFuncAttributeMaxDynamicSharedMemorySize, flash_smem);

    dim3 ggrid(EMB/128, MTOT/128, 3);
    qkv_gemm_mma<<<ggrid, 256, gemm_smem>>>(x, Wq, bq, Wk, bk, Wv, bv);

    const int rtot = 2*BATCH*NH*SEQ*32;
    rope_kernel<<<(rtot + 255)/256, 256>>>();

    dim3 fgrid(SEQ/128, NH, BATCH);
    flash_mma<<<fgrid, 128, flash_smem>>>(mask, out);
}